// round 15
// baseline (speedup 1.0000x reference)
#include <cuda_runtime.h>
#include <math.h>

#define Bn 8
#define Cn 64
#define On 64
#define Hn 128
#define Wn 128
#define HWn 16384
#define KKn 9
#define WR 8            // x-window rows staged in smem (B part)

typedef unsigned long long u64;

__device__ __forceinline__ u64 fma2(u64 a, u64 b, u64 c) {
    u64 d;
    asm("fma.rn.f32x2 %0,%1,%2,%3;" : "=l"(d) : "l"(a), "l"(b), "l"(c));
    return d;
}
__device__ __forceinline__ u64 dup2(float a) {
    u64 d;
    asm("mov.b64 %0,{%1,%1};" : "=l"(d) : "f"(a));
    return d;
}
__device__ __forceinline__ void unpack2(u64 v, float& lo, float& hi) {
    asm("mov.b64 {%0,%1},%2;" : "=f"(lo), "=f"(hi) : "l"(v));
}

// scratch
__device__ float g_mask[Bn * KKn * HWn];
__device__ float g_wT[576 * 64];     // deform weights [kk][o]
__device__ float g_pmT[576 * 36];    // offset+mask weights [kk][o]
__device__ int   g_done[Bn];         // per-batch A completion counters

// ---------------------------------------------------------------------------
// Prep: transpose weights + reset completion flags.
// ---------------------------------------------------------------------------
__global__ __launch_bounds__(256) void prep_kernel(
    const float* __restrict__ d_w,
    const float* __restrict__ p_w, const float* __restrict__ m_w)
{
    int e = blockIdx.x * 256 + threadIdx.x;
    if (e < Bn) g_done[e] = 0;
    if (e < 576 * 64) {
        int kk = e >> 6, o = e & 63;
        g_wT[e] = d_w[o * 576 + kk];
    }
    if (e < 576 * 36) {
        int kk = e / 36, o = e - kk * 36;
        float v = 0.f;
        if (o < 18)      v = p_w[o * 576 + kk];
        else if (o < 27) v = m_w[(o - 18) * 576 + kk];
        g_pmT[e] = v;
    }
}

// smem layout for B part (bytes):
#define SM_SA    0        // 72*128 f  = 36864
#define SM_SW    36864    // 72*64 f   = 18432
#define SM_SPOS  55296    // 1152 short= 2304
#define SM_SFLAG 57600    // 1152 B
#define SM_SWT   58752    // 1152 f4   = 18432
#define SM_SX    77184    // 8*8*128 f = 32768
#define SM_GUARD 109952   // 258 f     = 1032
#define SM_TOTAL 110984
// A part aliases (base of same buffer):
#define SM_AX    0        // 8*4*132 f = 16896
#define SM_AW    16896    // 72*36 f   = 10368

// ---------------------------------------------------------------------------
// Mega kernel: per batch, 64 A-blocks (2 rows each) then 128 B-blocks (1 row).
// B-blocks spin on g_done[b]==64 before consuming offsets/masks.
// ---------------------------------------------------------------------------
__global__ __launch_bounds__(256, 2) void mega_kernel(
    const float* __restrict__ x,
    const float* __restrict__ p_b, const float* __restrict__ m_b,
    const float* __restrict__ d_b,
    float* out, float* offs_out)
{
    extern __shared__ char smc[];
    const int bidx = blockIdx.x;
    const int b = bidx / 192;
    const int r = bidx - b * 192;
    const int tid = threadIdx.x;
    const int warp = tid >> 5, lane = tid & 31;

    if (r < 64) {
        // ================= A part: rows 2r, 2r+1 =================
        float (*sX)[4][132] = (float (*)[4][132])(smc + SM_AX);
        float* sW = (float*)(smc + SM_AW);
        const int h2 = r;
        const int px4 = ((warp & 3) * 8 + (lane & 7)) * 4;
        const int oc  = ((warp >> 2) * 4 + (lane >> 3)) * 4;
        const int i0  = px4 ? (px4 - 1) : 130;

        if (tid < 128) {
            int c = tid >> 4, rr = (tid >> 2) & 3, k = tid & 3;
            sX[c][rr][128 + k] = 0.f;
        }

        u64 acc2[2][4][2] = {};

        for (int c0 = 0; c0 < Cn; c0 += 8) {
            __syncthreads();
            #pragma unroll
            for (int j = 0; j < 4; ++j) {
                int e = tid + j * 256;
                int cr = e >> 5, q = e & 31;
                int c = cr >> 2, rr = cr & 3;
                int y = 2 * h2 - 1 + rr;
                float4 v = make_float4(0.f, 0.f, 0.f, 0.f);
                if ((unsigned)y < Hn)
                    v = *(const float4*)
                        (x + (((size_t)(b * Cn + c0 + c)) << 14) + y * Wn + q * 4);
                *(float4*)&sX[c][rr][q * 4] = v;
            }
            {
                const float4* src = (const float4*)(g_pmT + c0 * 9 * 36);
                for (int e = tid; e < 648; e += 256)
                    ((float4*)sW)[e] = src[e];
            }
            __syncthreads();

            #pragma unroll
            for (int c = 0; c < 8; ++c) {
                #pragma unroll
                for (int ki = 0; ki < 3; ++ki) {
                    const float* r0 = sX[c][ki];
                    const float* r1 = sX[c][ki + 1];
                    float4 Xa = *(const float4*)&r0[px4];
                    float4 Xb = *(const float4*)&r1[px4];
                    float xsA[6] = {r0[i0], Xa.x, Xa.y, Xa.z, Xa.w, r0[px4 + 4]};
                    float xsB[6] = {r1[i0], Xb.x, Xb.y, Xb.z, Xb.w, r1[px4 + 4]};
                    int kkb = c * 9 + ki * 3;
                    #pragma unroll
                    for (int kj = 0; kj < 3; ++kj) {
                        float4 wv = *(const float4*)&sW[(kkb + kj) * 36 + oc];
                        u64 wp0 = ((const u64*)&wv)[0];
                        u64 wp1 = ((const u64*)&wv)[1];
                        #pragma unroll
                        for (int q = 0; q < 4; ++q) {
                            u64 aA = dup2(xsA[q + kj]);
                            acc2[0][q][0] = fma2(aA, wp0, acc2[0][q][0]);
                            acc2[0][q][1] = fma2(aA, wp1, acc2[0][q][1]);
                            u64 aB = dup2(xsB[q + kj]);
                            acc2[1][q][0] = fma2(aB, wp0, acc2[1][q][0]);
                            acc2[1][q][1] = fma2(aB, wp1, acc2[1][q][1]);
                        }
                    }
                }
            }
        }

        #pragma unroll
        for (int rr = 0; rr < 2; ++rr) {
            int row = (2 * h2 + rr) * Wn;
            float acc[4][4];
            #pragma unroll
            for (int q = 0; q < 4; ++q) {
                unpack2(acc2[rr][q][0], acc[q][0], acc[q][1]);
                unpack2(acc2[rr][q][1], acc[q][2], acc[q][3]);
            }
            #pragma unroll
            for (int q = 0; q < 4; ++q) {
                int o = oc + q;
                if (o < 18) {
                    float bias = p_b[o];
                    float* dst = offs_out + (((size_t)(b * 18 + o)) << 14) + row;
                    float4 v = make_float4(acc[0][q] + bias, acc[1][q] + bias,
                                           acc[2][q] + bias, acc[3][q] + bias);
                    *(float4*)&dst[px4] = v;
                } else if (o < 27) {
                    float bias = m_b[o - 18];
                    float* dst = g_mask + (((size_t)(b * 9 + (o - 18))) << 14) + row;
                    float4 v;
                    v.x = 1.f / (1.f + expf(-(acc[0][q] + bias)));
                    v.y = 1.f / (1.f + expf(-(acc[1][q] + bias)));
                    v.z = 1.f / (1.f + expf(-(acc[2][q] + bias)));
                    v.w = 1.f / (1.f + expf(-(acc[3][q] + bias)));
                    *(float4*)&dst[px4] = v;
                }
            }
        }
        // release: batch-b offsets/masks are globally visible
        __syncthreads();
        __threadfence();
        if (tid == 0) atomicAdd(&g_done[b], 1);
        return;
    }

    // ================= B part: row h = r - 64 =================
    // acquire: wait until all 64 A-blocks of this batch have released
    if (tid == 0) {
        while (atomicAdd(&g_done[b], 0) < 64) __nanosleep(64);
    }
    __syncthreads();
    __threadfence();

    float* sA   = (float*)(smc + SM_SA);
    float* sW   = (float*)(smc + SM_SW);
    short* spos = (short*)(smc + SM_SPOS);
    unsigned char* sflag = (unsigned char*)(smc + SM_SFLAG);
    float4* swt = (float4*)(smc + SM_SWT);
    float* sX   = (float*)(smc + SM_SX);
    float* guard = (float*)(smc + SM_GUARD);
    const float* offs = offs_out;

    const int h = r - 64;
    const int px4 = ((warp & 3) * 8 + (lane & 7)) * 4;   // 4 pixels
    const int oc8 = ((warp >> 2) * 4 + (lane >> 3)) * 8; // 8 out channels
    const int row = h * Wn;
    const int ys = min(max(h - 3, 0), Hn - WR);          // window start row

    for (int e = tid; e < 258; e += 256) guard[e] = 0.f;

    // precompute: folded bilinear weights + window base index + fast flag
    for (int e = tid; e < KKn * Wn; e += 256) {
        int i = e & 127, k = e >> 7;
        float dy = offs[(((size_t)(b * 18 + 2 * k)) << 14) + row + i];
        float dx = offs[(((size_t)(b * 18 + 2 * k + 1)) << 14) + row + i];
        float m  = g_mask[(((size_t)(b * 9 + k)) << 14) + row + i];
        int ki = k / 3, kj = k - ki * 3;
        float py = (float)(h - 1 + ki) + dy;
        float px = (float)(i - 1 + kj) + dx;
        float y0f = floorf(py), x0f = floorf(px);
        float fy = py - y0f, fx = px - x0f;
        int y0 = (int)y0f, x0 = (int)x0f;
        int y1 = y0 + 1, x1 = x0 + 1;
        float vy0 = ((unsigned)y0 < Hn) ? 1.f : 0.f;
        float vy1 = ((unsigned)y1 < Hn) ? 1.f : 0.f;
        float vx0 = ((unsigned)x0 < Wn) ? 1.f : 0.f;
        float vx1 = ((unsigned)x1 < Wn) ? 1.f : 0.f;
        float gy = 1.f - fy, gx = 1.f - fx;
        float4 wq;
        wq.x = gy * gx * m * vy0 * vx0;
        wq.y = gy * fx * m * vy0 * vx1;
        wq.z = fy * gx * m * vy1 * vx0;
        wq.w = fy * fx * m * vy1 * vx1;
        int f0 = (y0 < 0) | (y0 > Hn - 1) | ((y0 >= ys) & (y0 <= ys + WR - 1));
        int f1 = (y1 < 0) | (y1 > Hn - 1) | ((y1 >= ys) & (y1 <= ys + WR - 1));
        int rr = min(max(y0 - ys, -1), WR);       // garbage-safe clamp
        int xb = min(max(x0, -1), Wn);
        spos[e]  = (short)(rr * Wn + xb);
        swt[e]   = wq;
        sflag[e] = (unsigned char)(f0 & f1);
    }

    const int px_g = tid & 127;         // gather: this thread's pixel
    const int hf   = tid >> 7;          // gather: channel half (0/1 -> 4 ch)

    u64 acc2[4][4] = {};                // [px][oc-pair]

    for (int c0 = 0; c0 < Cn; c0 += 8) {
        __syncthreads();   // prev GEMM done (and precompute done on iter 0)
        {
            const float4* src = (const float4*)(g_wT + c0 * 9 * 64);
            #pragma unroll 2
            for (int e = tid; e < 1152; e += 256)
                ((float4*)sW)[e] = src[e];
        }
        #pragma unroll
        for (int j = 0; j < 8; ++j) {
            int e = tid + j * 256;
            int c = e >> 8;
            int rem = e & 255;
            const float4* src = (const float4*)
                (x + (((size_t)(b * Cn + c0 + c)) << 14) + ys * Wn) + rem;
            ((float4*)sX)[(c << 8) + rem] = *src;
        }
        __syncthreads();

        {
            const float* sxc = sX + hf * 4 * (WR * Wn);
            const float* pg  = x + (((size_t)(b * Cn + c0 + hf * 4)) << 14);
            #pragma unroll
            for (int t = 0; t < KKn; ++t) {
                int   p0 = spos[t * 128 + px_g];
                float4 w4 = swt[t * 128 + px_g];
                int fast = sflag[t * 128 + px_g];
                if (__all_sync(0xffffffffu, fast)) {
                    #pragma unroll
                    for (int c = 0; c < 4; ++c) {
                        const float* s = sxc + c * (WR * Wn);
                        float v = w4.x * s[p0]       + w4.y * s[p0 + 1]
                                + w4.z * s[p0 + 128] + w4.w * s[p0 + 129];
                        sA[((hf * 4 + c) * 9 + t) * 128 + px_g] = v;
                    }
                } else {
                    float dy = offs[(((size_t)(b * 18 + 2 * t)) << 14) + row + px_g];
                    float dx = offs[(((size_t)(b * 18 + 2 * t + 1)) << 14) + row + px_g];
                    int ki = t / 3, kj = t - ki * 3;
                    float py = (float)(h - 1 + ki) + dy;
                    float px = (float)(px_g - 1 + kj) + dx;
                    int y0 = (int)floorf(py), x0 = (int)floorf(px);
                    int ry0 = min(max(y0, 0), Hn - 1) * Wn;
                    int ry1 = min(max(y0 + 1, 0), Hn - 1) * Wn;
                    int cx0 = min(max(x0, 0), Wn - 1);
                    int cx1 = min(max(x0 + 1, 0), Wn - 1);
                    int q0 = ry0 + cx0, q1 = ry0 + cx1;
                    int q2 = ry1 + cx0, q3 = ry1 + cx1;
                    #pragma unroll
                    for (int c = 0; c < 4; ++c) {
                        const float* p = pg + c * HWn;
                        float v = w4.x * __ldg(p + q0) + w4.y * __ldg(p + q1)
                                + w4.z * __ldg(p + q2) + w4.w * __ldg(p + q3);
                        sA[((hf * 4 + c) * 9 + t) * 128 + px_g] = v;
                    }
                }
            }
        }
        __syncthreads();

        #pragma unroll 4
        for (int kk = 0; kk < 72; ++kk) {
            float4 av = *(const float4*)&sA[kk * 128 + px4];
            float4 w0 = *(const float4*)&sW[kk * 64 + oc8];
            float4 w1 = *(const float4*)&sW[kk * 64 + oc8 + 4];
            u64 wp[4] = {((const u64*)&w0)[0], ((const u64*)&w0)[1],
                         ((const u64*)&w1)[0], ((const u64*)&w1)[1]};
            float ar[4] = {av.x, av.y, av.z, av.w};
            #pragma unroll
            for (int q = 0; q < 4; ++q) {
                u64 ad = dup2(ar[q]);
                #pragma unroll
                for (int p = 0; p < 4; ++p)
                    acc2[q][p] = fma2(ad, wp[p], acc2[q][p]);
            }
        }
    }

    float acc[4][8];
    #pragma unroll
    for (int q = 0; q < 4; ++q)
        #pragma unroll
        for (int p = 0; p < 4; ++p)
            unpack2(acc2[q][p], acc[q][2 * p], acc[q][2 * p + 1]);

    #pragma unroll
    for (int q = 0; q < 8; ++q) {
        int o = oc8 + q;
        float bias = __ldg(d_b + o);
        float* dst = out + (((size_t)(b * On + o)) << 14) + row;
        float4 v = make_float4(acc[0][q] + bias, acc[1][q] + bias,
                               acc[2][q] + bias, acc[3][q] + bias);
        *(float4*)&dst[px4] = v;
    }
}

// ---------------------------------------------------------------------------

extern "C" void kernel_launch(void* const* d_in, const int* in_sizes, int n_in,
                              void* d_out, int out_size) {
    const float* x    = (const float*)d_in[0];
    const float* p_w  = (const float*)d_in[1];
    const float* p_b  = (const float*)d_in[2];
    const float* m_w  = (const float*)d_in[3];
    const float* m_b  = (const float*)d_in[4];
    const float* d_wp = (const float*)d_in[5];
    const float* d_bp = (const float*)d_in[6];

    float* out = (float*)d_out;                         // [8,64,128,128]
    float* offs_out = out + (size_t)Bn * On * HWn;      // [8,18,128,128]

    cudaFuncSetAttribute(mega_kernel,
                         cudaFuncAttributeMaxDynamicSharedMemorySize, SM_TOTAL);

    prep_kernel<<<144, 256>>>(d_wp, p_w, m_w);
    mega_kernel<<<Bn * 192, 256, SM_TOTAL>>>(
        x, p_b, m_b, d_bp, out, offs_out);
}

// round 16
// speedup vs baseline: 1.2483x; 1.2483x over previous
#include <cuda_runtime.h>
#include <math.h>

#define Bn 8
#define Cn 64
#define On 64
#define Hn 128
#define Wn 128
#define HWn 16384
#define KKn 9
#define WR 8            // x-window rows staged in smem (B part)

typedef unsigned long long u64;

__device__ __forceinline__ u64 fma2(u64 a, u64 b, u64 c) {
    u64 d;
    asm("fma.rn.f32x2 %0,%1,%2,%3;" : "=l"(d) : "l"(a), "l"(b), "l"(c));
    return d;
}
__device__ __forceinline__ u64 dup2(float a) {
    u64 d;
    asm("mov.b64 %0,{%1,%1};" : "=l"(d) : "f"(a));
    return d;
}
__device__ __forceinline__ void unpack2(u64 v, float& lo, float& hi) {
    asm("mov.b64 {%0,%1},%2;" : "=f"(lo), "=f"(hi) : "l"(v));
}

// scratch
__device__ float g_mask[Bn * KKn * HWn];
__device__ float g_wT[576 * 64];     // deform weights [kk][o]
__device__ float g_pmT[576 * 36];    // offset+mask weights [kk][o]
__device__ int   g_done[Bn];         // per-batch A completion counters

// ---------------------------------------------------------------------------
// Prep: transpose weights + reset completion flags.
// ---------------------------------------------------------------------------
__global__ __launch_bounds__(256) void prep_kernel(
    const float* __restrict__ d_w,
    const float* __restrict__ p_w, const float* __restrict__ m_w)
{
    int e = blockIdx.x * 256 + threadIdx.x;
    if (e < Bn) g_done[e] = 0;
    if (e < 576 * 64) {
        int kk = e >> 6, o = e & 63;
        g_wT[e] = d_w[o * 576 + kk];
    }
    if (e < 576 * 36) {
        int kk = e / 36, o = e - kk * 36;
        float v = 0.f;
        if (o < 18)      v = p_w[o * 576 + kk];
        else if (o < 27) v = m_w[(o - 18) * 576 + kk];
        g_pmT[e] = v;
    }
}

// smem layout for B part (bytes):
#define SM_SA    0        // 72*128 f  = 36864
#define SM_SW    36864    // 72*64 f   = 18432
#define SM_SPOS  55296    // 1152 short= 2304
#define SM_SFLAG 57600    // 1152 B
#define SM_SWT   58752    // 1152 f4   = 18432
#define SM_SX    77184    // 8*8*128 f = 32768
#define SM_GUARD 109952   // 258 f     = 1032
#define SM_TOTAL 110984
// A part aliases (base of same buffer):
#define SM_AX    0        // 8*4*132 f = 16896
#define SM_AW    16896    // 72*36 f   = 10368

// ---------------------------------------------------------------------------
// Mega kernel v2: bids [0,512) = A-blocks (2 rows each, all batches),
// bids [512,1536) = B-blocks (1 row each). ALL A-blocks precede ALL B-blocks
// in dispatch order, so B's spin-wait on g_done[b] is near-zero for early
// batches and bounded for late ones; A-tail overlaps B-head (pipe mixing).
// ---------------------------------------------------------------------------
__global__ __launch_bounds__(256, 2) void mega_kernel(
    const float* __restrict__ x,
    const float* __restrict__ p_b, const float* __restrict__ m_b,
    const float* __restrict__ d_b,
    float* out, float* offs_out)
{
    extern __shared__ char smc[];
    const int bidx = blockIdx.x;
    const int tid = threadIdx.x;
    const int warp = tid >> 5, lane = tid & 31;

    if (bidx < 512) {
        // ================= A part: batch b, rows 2*h2, 2*h2+1 =============
        const int b = bidx >> 6;
        const int h2 = bidx & 63;
        float (*sX)[4][132] = (float (*)[4][132])(smc + SM_AX);
        float* sW = (float*)(smc + SM_AW);
        const int px4 = ((warp & 3) * 8 + (lane & 7)) * 4;
        const int oc  = ((warp >> 2) * 4 + (lane >> 3)) * 4;
        const int i0  = px4 ? (px4 - 1) : 130;

        if (tid < 128) {
            int c = tid >> 4, rr = (tid >> 2) & 3, k = tid & 3;
            sX[c][rr][128 + k] = 0.f;
        }

        u64 acc2[2][4][2] = {};

        for (int c0 = 0; c0 < Cn; c0 += 8) {
            __syncthreads();
            #pragma unroll
            for (int j = 0; j < 4; ++j) {
                int e = tid + j * 256;
                int cr = e >> 5, q = e & 31;
                int c = cr >> 2, rr = cr & 3;
                int y = 2 * h2 - 1 + rr;
                float4 v = make_float4(0.f, 0.f, 0.f, 0.f);
                if ((unsigned)y < Hn)
                    v = *(const float4*)
                        (x + (((size_t)(b * Cn + c0 + c)) << 14) + y * Wn + q * 4);
                *(float4*)&sX[c][rr][q * 4] = v;
            }
            {
                const float4* src = (const float4*)(g_pmT + c0 * 9 * 36);
                for (int e = tid; e < 648; e += 256)
                    ((float4*)sW)[e] = src[e];
            }
            __syncthreads();

            #pragma unroll
            for (int c = 0; c < 8; ++c) {
                #pragma unroll
                for (int ki = 0; ki < 3; ++ki) {
                    const float* r0 = sX[c][ki];
                    const float* r1 = sX[c][ki + 1];
                    float4 Xa = *(const float4*)&r0[px4];
                    float4 Xb = *(const float4*)&r1[px4];
                    float xsA[6] = {r0[i0], Xa.x, Xa.y, Xa.z, Xa.w, r0[px4 + 4]};
                    float xsB[6] = {r1[i0], Xb.x, Xb.y, Xb.z, Xb.w, r1[px4 + 4]};
                    int kkb = c * 9 + ki * 3;
                    #pragma unroll
                    for (int kj = 0; kj < 3; ++kj) {
                        float4 wv = *(const float4*)&sW[(kkb + kj) * 36 + oc];
                        u64 wp0 = ((const u64*)&wv)[0];
                        u64 wp1 = ((const u64*)&wv)[1];
                        #pragma unroll
                        for (int q = 0; q < 4; ++q) {
                            u64 aA = dup2(xsA[q + kj]);
                            acc2[0][q][0] = fma2(aA, wp0, acc2[0][q][0]);
                            acc2[0][q][1] = fma2(aA, wp1, acc2[0][q][1]);
                            u64 aB = dup2(xsB[q + kj]);
                            acc2[1][q][0] = fma2(aB, wp0, acc2[1][q][0]);
                            acc2[1][q][1] = fma2(aB, wp1, acc2[1][q][1]);
                        }
                    }
                }
            }
        }

        #pragma unroll
        for (int rr = 0; rr < 2; ++rr) {
            int row = (2 * h2 + rr) * Wn;
            float acc[4][4];
            #pragma unroll
            for (int q = 0; q < 4; ++q) {
                unpack2(acc2[rr][q][0], acc[q][0], acc[q][1]);
                unpack2(acc2[rr][q][1], acc[q][2], acc[q][3]);
            }
            #pragma unroll
            for (int q = 0; q < 4; ++q) {
                int o = oc + q;
                if (o < 18) {
                    float bias = p_b[o];
                    float* dst = offs_out + (((size_t)(b * 18 + o)) << 14) + row;
                    float4 v = make_float4(acc[0][q] + bias, acc[1][q] + bias,
                                           acc[2][q] + bias, acc[3][q] + bias);
                    *(float4*)&dst[px4] = v;
                } else if (o < 27) {
                    float bias = m_b[o - 18];
                    float* dst = g_mask + (((size_t)(b * 9 + (o - 18))) << 14) + row;
                    float4 v;
                    v.x = 1.f / (1.f + expf(-(acc[0][q] + bias)));
                    v.y = 1.f / (1.f + expf(-(acc[1][q] + bias)));
                    v.z = 1.f / (1.f + expf(-(acc[2][q] + bias)));
                    v.w = 1.f / (1.f + expf(-(acc[3][q] + bias)));
                    *(float4*)&dst[px4] = v;
                }
            }
        }
        // release: batch-b offsets/masks are globally visible
        __syncthreads();
        __threadfence();
        if (tid == 0) atomicAdd(&g_done[b], 1);
        return;
    }

    // ================= B part: batch b, row h =================
    const int e2 = bidx - 512;
    const int b = e2 >> 7;
    const int h = e2 & 127;

    // acquire: wait until all 64 A-blocks of this batch have released
    if (tid == 0) {
        while (atomicAdd(&g_done[b], 0) < 64) __nanosleep(64);
    }
    __syncthreads();
    __threadfence();

    float* sA   = (float*)(smc + SM_SA);
    float* sW   = (float*)(smc + SM_SW);
    short* spos = (short*)(smc + SM_SPOS);
    unsigned char* sflag = (unsigned char*)(smc + SM_SFLAG);
    float4* swt = (float4*)(smc + SM_SWT);
    float* sX   = (float*)(smc + SM_SX);
    float* guard = (float*)(smc + SM_GUARD);
    const float* offs = offs_out;

    const int px4 = ((warp & 3) * 8 + (lane & 7)) * 4;   // 4 pixels
    const int oc8 = ((warp >> 2) * 4 + (lane >> 3)) * 8; // 8 out channels
    const int row = h * Wn;
    const int ys = min(max(h - 3, 0), Hn - WR);          // window start row

    for (int e = tid; e < 258; e += 256) guard[e] = 0.f;

    // precompute: folded bilinear weights + window base index + fast flag
    for (int e = tid; e < KKn * Wn; e += 256) {
        int i = e & 127, k = e >> 7;
        float dy = offs[(((size_t)(b * 18 + 2 * k)) << 14) + row + i];
        float dx = offs[(((size_t)(b * 18 + 2 * k + 1)) << 14) + row + i];
        float m  = g_mask[(((size_t)(b * 9 + k)) << 14) + row + i];
        int ki = k / 3, kj = k - ki * 3;
        float py = (float)(h - 1 + ki) + dy;
        float px = (float)(i - 1 + kj) + dx;
        float y0f = floorf(py), x0f = floorf(px);
        float fy = py - y0f, fx = px - x0f;
        int y0 = (int)y0f, x0 = (int)x0f;
        int y1 = y0 + 1, x1 = x0 + 1;
        float vy0 = ((unsigned)y0 < Hn) ? 1.f : 0.f;
        float vy1 = ((unsigned)y1 < Hn) ? 1.f : 0.f;
        float vx0 = ((unsigned)x0 < Wn) ? 1.f : 0.f;
        float vx1 = ((unsigned)x1 < Wn) ? 1.f : 0.f;
        float gy = 1.f - fy, gx = 1.f - fx;
        float4 wq;
        wq.x = gy * gx * m * vy0 * vx0;
        wq.y = gy * fx * m * vy0 * vx1;
        wq.z = fy * gx * m * vy1 * vx0;
        wq.w = fy * fx * m * vy1 * vx1;
        int f0 = (y0 < 0) | (y0 > Hn - 1) | ((y0 >= ys) & (y0 <= ys + WR - 1));
        int f1 = (y1 < 0) | (y1 > Hn - 1) | ((y1 >= ys) & (y1 <= ys + WR - 1));
        int rr = min(max(y0 - ys, -1), WR);       // garbage-safe clamp
        int xb = min(max(x0, -1), Wn);
        spos[e]  = (short)(rr * Wn + xb);
        swt[e]   = wq;
        sflag[e] = (unsigned char)(f0 & f1);
    }

    const int px_g = tid & 127;         // gather: this thread's pixel
    const int hf   = tid >> 7;          // gather: channel half (0/1 -> 4 ch)

    u64 acc2[4][4] = {};                // [px][oc-pair]

    for (int c0 = 0; c0 < Cn; c0 += 8) {
        __syncthreads();   // prev GEMM done (and precompute done on iter 0)
        {
            const float4* src = (const float4*)(g_wT + c0 * 9 * 64);
            #pragma unroll 2
            for (int e = tid; e < 1152; e += 256)
                ((float4*)sW)[e] = src[e];
        }
        #pragma unroll
        for (int j = 0; j < 8; ++j) {
            int e = tid + j * 256;
            int c = e >> 8;
            int rem = e & 255;
            const float4* src = (const float4*)
                (x + (((size_t)(b * Cn + c0 + c)) << 14) + ys * Wn) + rem;
            ((float4*)sX)[(c << 8) + rem] = *src;
        }
        __syncthreads();

        {
            const float* sxc = sX + hf * 4 * (WR * Wn);
            const float* pg  = x + (((size_t)(b * Cn + c0 + hf * 4)) << 14);
            #pragma unroll
            for (int t = 0; t < KKn; ++t) {
                int   p0 = spos[t * 128 + px_g];
                float4 w4 = swt[t * 128 + px_g];
                int fast = sflag[t * 128 + px_g];
                if (__all_sync(0xffffffffu, fast)) {
                    #pragma unroll
                    for (int c = 0; c < 4; ++c) {
                        const float* s = sxc + c * (WR * Wn);
                        float v = w4.x * s[p0]       + w4.y * s[p0 + 1]
                                + w4.z * s[p0 + 128] + w4.w * s[p0 + 129];
                        sA[((hf * 4 + c) * 9 + t) * 128 + px_g] = v;
                    }
                } else {
                    float dy = offs[(((size_t)(b * 18 + 2 * t)) << 14) + row + px_g];
                    float dx = offs[(((size_t)(b * 18 + 2 * t + 1)) << 14) + row + px_g];
                    int ki = t / 3, kj = t - ki * 3;
                    float py = (float)(h - 1 + ki) + dy;
                    float px = (float)(px_g - 1 + kj) + dx;
                    int y0 = (int)floorf(py), x0 = (int)floorf(px);
                    int ry0 = min(max(y0, 0), Hn - 1) * Wn;
                    int ry1 = min(max(y0 + 1, 0), Hn - 1) * Wn;
                    int cx0 = min(max(x0, 0), Wn - 1);
                    int cx1 = min(max(x0 + 1, 0), Wn - 1);
                    int q0 = ry0 + cx0, q1 = ry0 + cx1;
                    int q2 = ry1 + cx0, q3 = ry1 + cx1;
                    #pragma unroll
                    for (int c = 0; c < 4; ++c) {
                        const float* p = pg + c * HWn;
                        float v = w4.x * __ldg(p + q0) + w4.y * __ldg(p + q1)
                                + w4.z * __ldg(p + q2) + w4.w * __ldg(p + q3);
                        sA[((hf * 4 + c) * 9 + t) * 128 + px_g] = v;
                    }
                }
            }
        }
        __syncthreads();

        #pragma unroll 4
        for (int kk = 0; kk < 72; ++kk) {
            float4 av = *(const float4*)&sA[kk * 128 + px4];
            float4 w0 = *(const float4*)&sW[kk * 64 + oc8];
            float4 w1 = *(const float4*)&sW[kk * 64 + oc8 + 4];
            u64 wp[4] = {((const u64*)&w0)[0], ((const u64*)&w0)[1],
                         ((const u64*)&w1)[0], ((const u64*)&w1)[1]};
            float ar[4] = {av.x, av.y, av.z, av.w};
            #pragma unroll
            for (int q = 0; q < 4; ++q) {
                u64 ad = dup2(ar[q]);
                #pragma unroll
                for (int p = 0; p < 4; ++p)
                    acc2[q][p] = fma2(ad, wp[p], acc2[q][p]);
            }
        }
    }

    float acc[4][8];
    #pragma unroll
    for (int q = 0; q < 4; ++q)
        #pragma unroll
        for (int p = 0; p < 4; ++p)
            unpack2(acc2[q][p], acc[q][2 * p], acc[q][2 * p + 1]);

    #pragma unroll
    for (int q = 0; q < 8; ++q) {
        int o = oc8 + q;
        float bias = __ldg(d_b + o);
        float* dst = out + (((size_t)(b * On + o)) << 14) + row;
        float4 v = make_float4(acc[0][q] + bias, acc[1][q] + bias,
                               acc[2][q] + bias, acc[3][q] + bias);
        *(float4*)&dst[px4] = v;
    }
}

// ---------------------------------------------------------------------------

extern "C" void kernel_launch(void* const* d_in, const int* in_sizes, int n_in,
                              void* d_out, int out_size) {
    const float* x    = (const float*)d_in[0];
    const float* p_w  = (const float*)d_in[1];
    const float* p_b  = (const float*)d_in[2];
    const float* m_w  = (const float*)d_in[3];
    const float* m_b  = (const float*)d_in[4];
    const float* d_wp = (const float*)d_in[5];
    const float* d_bp = (const float*)d_in[6];

    float* out = (float*)d_out;                         // [8,64,128,128]
    float* offs_out = out + (size_t)Bn * On * HWn;      // [8,18,128,128]

    cudaFuncSetAttribute(mega_kernel,
                         cudaFuncAttributeMaxDynamicSharedMemorySize, SM_TOTAL);

    prep_kernel<<<144, 256>>>(d_wp, p_w, m_w);
    mega_kernel<<<Bn * 192, 256, SM_TOTAL>>>(
        x, p_b, m_b, d_bp, out, offs_out);
}

// round 17
// speedup vs baseline: 1.3045x; 1.0450x over previous
#include <cuda_runtime.h>
#include <math.h>

#define Bn 8
#define Cn 64
#define On 64
#define Hn 128
#define Wn 128
#define HWn 16384
#define KKn 9
#define WR 8            // x-window rows staged in smem (B part)

typedef unsigned long long u64;

__device__ __forceinline__ u64 fma2(u64 a, u64 b, u64 c) {
    u64 d;
    asm("fma.rn.f32x2 %0,%1,%2,%3;" : "=l"(d) : "l"(a), "l"(b), "l"(c));
    return d;
}
__device__ __forceinline__ u64 dup2(float a) {
    u64 d;
    asm("mov.b64 %0,{%1,%1};" : "=l"(d) : "f"(a));
    return d;
}
__device__ __forceinline__ void unpack2(u64 v, float& lo, float& hi) {
    asm("mov.b64 {%0,%1},%2;" : "=f"(lo), "=f"(hi) : "l"(v));
}

// scratch
__device__ float g_mask[Bn * KKn * HWn];
__device__ float g_wT[576 * 64];     // deform weights [kk][o]
__device__ float g_pmT[576 * 36];    // offset+mask weights [kk][o]
__device__ int   g_done[Bn];         // per-batch A completion counters

// ---------------------------------------------------------------------------
// Prep: transpose weights + reset completion flags.
// ---------------------------------------------------------------------------
__global__ __launch_bounds__(256) void prep_kernel(
    const float* __restrict__ d_w,
    const float* __restrict__ p_w, const float* __restrict__ m_w)
{
    int e = blockIdx.x * 256 + threadIdx.x;
    if (e < Bn) g_done[e] = 0;
    if (e < 576 * 64) {
        int kk = e >> 6, o = e & 63;
        g_wT[e] = d_w[o * 576 + kk];
    }
    if (e < 576 * 36) {
        int kk = e / 36, o = e - kk * 36;
        float v = 0.f;
        if (o < 18)      v = p_w[o * 576 + kk];
        else if (o < 27) v = m_w[(o - 18) * 576 + kk];
        g_pmT[e] = v;
    }
}

// smem layout for B part (bytes):
#define SM_SA    0        // 72*128 f  = 36864
#define SM_SW    36864    // 72*64 f   = 18432
#define SM_SPOS  55296    // 1152 short= 2304 (flag packed in LSB)
#define SM_SWT   58752    // 1152 f4   = 18432
#define SM_SX    77184    // 8*8*128 f = 32768
#define SM_GUARD 109952   // 258 f     = 1032
#define SM_TOTAL 110984
// A part aliases (base of same buffer):
#define SM_AX    0        // 8*4*132 f = 16896
#define SM_AW    16896    // 72*36 f   = 10368

// ---------------------------------------------------------------------------
// Mega kernel v3: bids [0,512) = A-blocks (2 rows each), [512,1536) =
// B-blocks (1 row). All A precede all B in dispatch order. B: chunk-0
// staging hoisted above the acquire spin; gather metadata (p0,flag)
// register-cached across all 8 chunks.
// ---------------------------------------------------------------------------
__global__ __launch_bounds__(256, 2) void mega_kernel(
    const float* __restrict__ x,
    const float* __restrict__ p_b, const float* __restrict__ m_b,
    const float* __restrict__ d_b,
    float* out, float* offs_out)
{
    extern __shared__ char smc[];
    const int bidx = blockIdx.x;
    const int tid = threadIdx.x;
    const int warp = tid >> 5, lane = tid & 31;

    if (bidx < 512) {
        // ================= A part: batch b, rows 2*h2, 2*h2+1 =============
        const int b = bidx >> 6;
        const int h2 = bidx & 63;
        float (*sX)[4][132] = (float (*)[4][132])(smc + SM_AX);
        float* sW = (float*)(smc + SM_AW);
        const int px4 = ((warp & 3) * 8 + (lane & 7)) * 4;
        const int oc  = ((warp >> 2) * 4 + (lane >> 3)) * 4;
        const int i0  = px4 ? (px4 - 1) : 130;

        if (tid < 128) {
            int c = tid >> 4, rr = (tid >> 2) & 3, k = tid & 3;
            sX[c][rr][128 + k] = 0.f;
        }

        u64 acc2[2][4][2] = {};

        for (int c0 = 0; c0 < Cn; c0 += 8) {
            __syncthreads();
            #pragma unroll
            for (int j = 0; j < 4; ++j) {
                int e = tid + j * 256;
                int cr = e >> 5, q = e & 31;
                int c = cr >> 2, rr = cr & 3;
                int y = 2 * h2 - 1 + rr;
                float4 v = make_float4(0.f, 0.f, 0.f, 0.f);
                if ((unsigned)y < Hn)
                    v = *(const float4*)
                        (x + (((size_t)(b * Cn + c0 + c)) << 14) + y * Wn + q * 4);
                *(float4*)&sX[c][rr][q * 4] = v;
            }
            {
                const float4* src = (const float4*)(g_pmT + c0 * 9 * 36);
                for (int e = tid; e < 648; e += 256)
                    ((float4*)sW)[e] = src[e];
            }
            __syncthreads();

            #pragma unroll
            for (int c = 0; c < 8; ++c) {
                #pragma unroll
                for (int ki = 0; ki < 3; ++ki) {
                    const float* r0 = sX[c][ki];
                    const float* r1 = sX[c][ki + 1];
                    float4 Xa = *(const float4*)&r0[px4];
                    float4 Xb = *(const float4*)&r1[px4];
                    float xsA[6] = {r0[i0], Xa.x, Xa.y, Xa.z, Xa.w, r0[px4 + 4]};
                    float xsB[6] = {r1[i0], Xb.x, Xb.y, Xb.z, Xb.w, r1[px4 + 4]};
                    int kkb = c * 9 + ki * 3;
                    #pragma unroll
                    for (int kj = 0; kj < 3; ++kj) {
                        float4 wv = *(const float4*)&sW[(kkb + kj) * 36 + oc];
                        u64 wp0 = ((const u64*)&wv)[0];
                        u64 wp1 = ((const u64*)&wv)[1];
                        #pragma unroll
                        for (int q = 0; q < 4; ++q) {
                            u64 aA = dup2(xsA[q + kj]);
                            acc2[0][q][0] = fma2(aA, wp0, acc2[0][q][0]);
                            acc2[0][q][1] = fma2(aA, wp1, acc2[0][q][1]);
                            u64 aB = dup2(xsB[q + kj]);
                            acc2[1][q][0] = fma2(aB, wp0, acc2[1][q][0]);
                            acc2[1][q][1] = fma2(aB, wp1, acc2[1][q][1]);
                        }
                    }
                }
            }
        }

        #pragma unroll
        for (int rr = 0; rr < 2; ++rr) {
            int row = (2 * h2 + rr) * Wn;
            float acc[4][4];
            #pragma unroll
            for (int q = 0; q < 4; ++q) {
                unpack2(acc2[rr][q][0], acc[q][0], acc[q][1]);
                unpack2(acc2[rr][q][1], acc[q][2], acc[q][3]);
            }
            #pragma unroll
            for (int q = 0; q < 4; ++q) {
                int o = oc + q;
                if (o < 18) {
                    float bias = p_b[o];
                    float* dst = offs_out + (((size_t)(b * 18 + o)) << 14) + row;
                    float4 v = make_float4(acc[0][q] + bias, acc[1][q] + bias,
                                           acc[2][q] + bias, acc[3][q] + bias);
                    *(float4*)&dst[px4] = v;
                } else if (o < 27) {
                    float bias = m_b[o - 18];
                    float* dst = g_mask + (((size_t)(b * 9 + (o - 18))) << 14) + row;
                    float4 v;
                    v.x = 1.f / (1.f + expf(-(acc[0][q] + bias)));
                    v.y = 1.f / (1.f + expf(-(acc[1][q] + bias)));
                    v.z = 1.f / (1.f + expf(-(acc[2][q] + bias)));
                    v.w = 1.f / (1.f + expf(-(acc[3][q] + bias)));
                    *(float4*)&dst[px4] = v;
                }
            }
        }
        __syncthreads();
        __threadfence();
        if (tid == 0) atomicAdd(&g_done[b], 1);
        return;
    }

    // ================= B part: batch b, row h =================
    const int e2 = bidx - 512;
    const int b = e2 >> 7;
    const int h = e2 & 127;

    float* sA   = (float*)(smc + SM_SA);
    float* sW   = (float*)(smc + SM_SW);
    short* spos = (short*)(smc + SM_SPOS);
    float4* swt = (float4*)(smc + SM_SWT);
    float* sX   = (float*)(smc + SM_SX);
    float* guard = (float*)(smc + SM_GUARD);
    const float* offs = offs_out;

    const int px4 = ((warp & 3) * 8 + (lane & 7)) * 4;   // 4 pixels
    const int oc8 = ((warp >> 2) * 4 + (lane >> 3)) * 8; // 8 out channels
    const int row = h * Wn;
    const int ys = min(max(h - 3, 0), Hn - WR);          // window start row

    // --- stage chunk 0 (independent of A's output) BEFORE the acquire ---
    {
        const float4* src = (const float4*)(g_wT);
        #pragma unroll 2
        for (int e = tid; e < 1152; e += 256)
            ((float4*)sW)[e] = src[e];
        #pragma unroll
        for (int j = 0; j < 8; ++j) {
            int e = tid + j * 256;
            int c = e >> 8;
            int rem = e & 255;
            const float4* s2 = (const float4*)
                (x + (((size_t)(b * Cn + c)) << 14) + ys * Wn) + rem;
            ((float4*)sX)[(c << 8) + rem] = *s2;
        }
        for (int e = tid; e < 258; e += 256) guard[e] = 0.f;
    }

    // acquire: wait until all 64 A-blocks of this batch have released
    if (tid == 0) {
        while (atomicAdd(&g_done[b], 0) < 64) __nanosleep(64);
    }
    __syncthreads();
    __threadfence();

    // precompute: folded bilinear weights + packed (base index, flag)
    for (int e = tid; e < KKn * Wn; e += 256) {
        int i = e & 127, k = e >> 7;
        float dy = offs[(((size_t)(b * 18 + 2 * k)) << 14) + row + i];
        float dx = offs[(((size_t)(b * 18 + 2 * k + 1)) << 14) + row + i];
        float m  = g_mask[(((size_t)(b * 9 + k)) << 14) + row + i];
        int ki = k / 3, kj = k - ki * 3;
        float py = (float)(h - 1 + ki) + dy;
        float px = (float)(i - 1 + kj) + dx;
        float y0f = floorf(py), x0f = floorf(px);
        float fy = py - y0f, fx = px - x0f;
        int y0 = (int)y0f, x0 = (int)x0f;
        int y1 = y0 + 1, x1 = x0 + 1;
        float vy0 = ((unsigned)y0 < Hn) ? 1.f : 0.f;
        float vy1 = ((unsigned)y1 < Hn) ? 1.f : 0.f;
        float vx0 = ((unsigned)x0 < Wn) ? 1.f : 0.f;
        float vx1 = ((unsigned)x1 < Wn) ? 1.f : 0.f;
        float gy = 1.f - fy, gx = 1.f - fx;
        float4 wq;
        wq.x = gy * gx * m * vy0 * vx0;
        wq.y = gy * fx * m * vy0 * vx1;
        wq.z = fy * gx * m * vy1 * vx0;
        wq.w = fy * fx * m * vy1 * vx1;
        int f0 = (y0 < 0) | (y0 > Hn - 1) | ((y0 >= ys) & (y0 <= ys + WR - 1));
        int f1 = (y1 < 0) | (y1 > Hn - 1) | ((y1 >= ys) & (y1 <= ys + WR - 1));
        int rr = min(max(y0 - ys, -1), WR);       // garbage-safe clamp
        int xb = min(max(x0, -1), Wn);
        spos[e] = (short)((((rr * Wn + xb)) << 1) | (f0 & f1));
        swt[e]  = wq;
    }
    __syncthreads();   // precompute + chunk-0 staging visible to all

    const int px_g = tid & 127;         // gather: this thread's pixel
    const int hf   = tid >> 7;          // gather: channel half (0/1 -> 4 ch)

    // register-cache (p0, flag) for this thread's pixel across all chunks
    int p0r[KKn];
    unsigned fmask = 0;
    #pragma unroll
    for (int t = 0; t < KKn; ++t) {
        int s = spos[t * 128 + px_g];
        p0r[t] = s >> 1;
        fmask |= (unsigned)(s & 1) << t;
    }

    u64 acc2[4][4] = {};                // [px][oc-pair]

    for (int n = 0; n < 8; ++n) {
        const int c0 = n * 8;
        // gather: thread = (pixel, 4-channel half); conflict-free LDS
        {
            const float* sxc = sX + hf * 4 * (WR * Wn);
            const float* pg  = x + (((size_t)(b * Cn + c0 + hf * 4)) << 14);
            #pragma unroll
            for (int t = 0; t < KKn; ++t) {
                int   p0 = p0r[t];
                float4 w4 = swt[t * 128 + px_g];
                int fast = (fmask >> t) & 1;
                if (__all_sync(0xffffffffu, fast)) {
                    #pragma unroll
                    for (int c = 0; c < 4; ++c) {
                        const float* s = sxc + c * (WR * Wn);
                        float v = w4.x * s[p0]       + w4.y * s[p0 + 1]
                                + w4.z * s[p0 + 128] + w4.w * s[p0 + 129];
                        sA[((hf * 4 + c) * 9 + t) * 128 + px_g] = v;
                    }
                } else {
                    float dy = offs[(((size_t)(b * 18 + 2 * t)) << 14) + row + px_g];
                    float dx = offs[(((size_t)(b * 18 + 2 * t + 1)) << 14) + row + px_g];
                    int ki = t / 3, kj = t - ki * 3;
                    float py = (float)(h - 1 + ki) + dy;
                    float px = (float)(px_g - 1 + kj) + dx;
                    int y0 = (int)floorf(py), x0 = (int)floorf(px);
                    int ry0 = min(max(y0, 0), Hn - 1) * Wn;
                    int ry1 = min(max(y0 + 1, 0), Hn - 1) * Wn;
                    int cx0 = min(max(x0, 0), Wn - 1);
                    int cx1 = min(max(x0 + 1, 0), Wn - 1);
                    int q0 = ry0 + cx0, q1 = ry0 + cx1;
                    int q2 = ry1 + cx0, q3 = ry1 + cx1;
                    #pragma unroll
                    for (int c = 0; c < 4; ++c) {
                        const float* p = pg + c * HWn;
                        float v = w4.x * __ldg(p + q0) + w4.y * __ldg(p + q1)
                                + w4.z * __ldg(p + q2) + w4.w * __ldg(p + q3);
                        sA[((hf * 4 + c) * 9 + t) * 128 + px_g] = v;
                    }
                }
            }
        }
        __syncthreads();    // sA ready

        #pragma unroll 4
        for (int kk = 0; kk < 72; ++kk) {
            float4 av = *(const float4*)&sA[kk * 128 + px4];
            float4 w0 = *(const float4*)&sW[kk * 64 + oc8];
            float4 w1 = *(const float4*)&sW[kk * 64 + oc8 + 4];
            u64 wp[4] = {((const u64*)&w0)[0], ((const u64*)&w0)[1],
                         ((const u64*)&w1)[0], ((const u64*)&w1)[1]};
            float ar[4] = {av.x, av.y, av.z, av.w};
            #pragma unroll
            for (int q = 0; q < 4; ++q) {
                u64 ad = dup2(ar[q]);
                #pragma unroll
                for (int p = 0; p < 4; ++p)
                    acc2[q][p] = fma2(ad, wp[p], acc2[q][p]);
            }
        }

        if (n < 7) {
            __syncthreads();    // gemm done before overwriting sW/sX
            const int c1 = c0 + 8;
            {
                const float4* src = (const float4*)(g_wT + c1 * 9 * 64);
                #pragma unroll 2
                for (int e = tid; e < 1152; e += 256)
                    ((float4*)sW)[e] = src[e];
            }
            #pragma unroll
            for (int j = 0; j < 8; ++j) {
                int e = tid + j * 256;
                int c = e >> 8;
                int rem = e & 255;
                const float4* s2 = (const float4*)
                    (x + (((size_t)(b * Cn + c1 + c)) << 14) + ys * Wn) + rem;
                ((float4*)sX)[(c << 8) + rem] = *s2;
            }
            __syncthreads();    // staged before next gather
        }
    }

    float acc[4][8];
    #pragma unroll
    for (int q = 0; q < 4; ++q)
        #pragma unroll
        for (int p = 0; p < 4; ++p)
            unpack2(acc2[q][p], acc[q][2 * p], acc[q][2 * p + 1]);

    #pragma unroll
    for (int q = 0; q < 8; ++q) {
        int o = oc8 + q;
        float bias = __ldg(d_b + o);
        float* dst = out + (((size_t)(b * On + o)) << 14) + row;
        float4 v = make_float4(acc[0][q] + bias, acc[1][q] + bias,
                               acc[2][q] + bias, acc[3][q] + bias);
        *(float4*)&dst[px4] = v;
    }
}

// ---------------------------------------------------------------------------

extern "C" void kernel_launch(void* const* d_in, const int* in_sizes, int n_in,
                              void* d_out, int out_size) {
    const float* x    = (const float*)d_in[0];
    const float* p_w  = (const float*)d_in[1];
    const float* p_b  = (const float*)d_in[2];
    const float* m_w  = (const float*)d_in[3];
    const float* m_b  = (const float*)d_in[4];
    const float* d_wp = (const float*)d_in[5];
    const float* d_bp = (const float*)d_in[6];

    float* out = (float*)d_out;                         // [8,64,128,128]
    float* offs_out = out + (size_t)Bn * On * HWn;      // [8,18,128,128]

    cudaFuncSetAttribute(mega_kernel,
                         cudaFuncAttributeMaxDynamicSharedMemorySize, SM_TOTAL);

    prep_kernel<<<144, 256>>>(d_wp, p_w, m_w);
    mega_kernel<<<Bn * 192, 256, SM_TOTAL>>>(
        x, p_b, m_b, d_bp, out, offs_out);
}